// round 2
// baseline (speedup 1.0000x reference)
#include <cuda_runtime.h>
#include <cuda_bf16.h>

#define CONFIDENCE_F 0.95f
#define SMOOTHING_F  0.05f
#define B_MAX 65536
#define C_DIM 2048                 // floats per row
#define F4_PER_ROW (C_DIM / 4)     // 512 float4

// Deterministic per-row partials (loss_i, w_i). __device__ global = allowed scratch.
__device__ float2 g_part[B_MAX];
__device__ int    g_is64;          // 1 if target buffer is int64, 0 if int32

__device__ __forceinline__ float pick4(float4 v, int c) {
    float r = v.x;
    if (c == 1) r = v.y;
    if (c == 2) r = v.z;
    if (c == 3) r = v.w;
    return r;
}

// Detect target dtype by inspecting the first nwords int32 words (safe to read
// under either dtype: int64 buffer is 2x as large). int64 little-endian with
// values < 2048 means every odd word is 0; random int32 targets make that
// essentially impossible.
__global__ void detect_t64_kernel(const int* __restrict__ t, int nwords)
{
    __shared__ int any_nz;
    if (threadIdx.x == 0) any_nz = 0;
    __syncthreads();
    int local = 0;
    for (int i = 1 + 2 * threadIdx.x; i < nwords; i += 2 * blockDim.x)
        if (t[i] != 0) local = 1;
    if (local) any_nz = 1;     // benign idempotent write
    __syncthreads();
    if (threadIdx.x == 0) g_is64 = any_nz ? 0 : 1;
}

__global__ __launch_bounds__(256)
void ls_row_kernel(const float4* __restrict__ x,
                   const void* __restrict__ tgt,
                   const float* __restrict__ w)
{
    __shared__ float s_max[8];
    __shared__ float s_se[8];
    __shared__ float s_sx[8];
    __shared__ float s_xt;

    const int row = blockIdx.x;
    const int tid = threadIdx.x;
    const int wid = tid >> 5;
    const int lid = tid & 31;

    const float4* xr = x + (size_t)row * F4_PER_ROW;

    // Two fully-coalesced 128-bit loads: elements [tid*4, tid*4+4) and [1024 + tid*4, ...)
    float4 a = xr[tid];
    float4 b = xr[tid + 256];

    int ti;
    if (g_is64) ti = (int)((const long long*)tgt)[row];
    else        ti = ((const int*)tgt)[row];
    ti = min(max(ti, 0), C_DIM - 1);   // crash-proofing; wrong dtype -> loud rel_err

    // local max + local sum(x)
    float mx = fmaxf(fmaxf(fmaxf(a.x, a.y), fmaxf(a.z, a.w)),
                     fmaxf(fmaxf(b.x, b.y), fmaxf(b.z, b.w)));
    float sx = ((a.x + a.y) + (a.z + a.w)) + ((b.x + b.y) + (b.z + b.w));

    // warp max reduce
    #pragma unroll
    for (int o = 16; o; o >>= 1)
        mx = fmaxf(mx, __shfl_xor_sync(0xffffffff, mx, o));
    if (lid == 0) s_max[wid] = mx;

    // the thread owning element ti publishes x[ti]
    if (ti < 1024) {
        if ((ti >> 2) == tid) s_xt = pick4(a, ti & 3);
    } else {
        if (((ti - 1024) >> 2) == tid) s_xt = pick4(b, ti & 3);
    }
    __syncthreads();

    float m = s_max[0];
    #pragma unroll
    for (int i = 1; i < 8; i++) m = fmaxf(m, s_max[i]);

    // sum of exp(x - m) from registers (no second gmem read)
    float se = __expf(a.x - m) + __expf(a.y - m) + __expf(a.z - m) + __expf(a.w - m)
             + __expf(b.x - m) + __expf(b.y - m) + __expf(b.z - m) + __expf(b.w - m);

    #pragma unroll
    for (int o = 16; o; o >>= 1) {
        se += __shfl_xor_sync(0xffffffff, se, o);
        sx += __shfl_xor_sync(0xffffffff, sx, o);
    }
    if (lid == 0) { s_se[wid] = se; s_sx[wid] = sx; }
    __syncthreads();

    if (tid == 0) {
        float se_t = 0.f, sx_t = 0.f;
        #pragma unroll
        for (int i = 0; i < 8; i++) { se_t += s_se[i]; sx_t += s_sx[i]; }
        float lse    = m + __logf(se_t);
        float nll    = lse - s_xt;                     // -logprob[target]
        float smooth = lse - sx_t * (1.0f / C_DIM);    // -mean(logprobs)
        float wt     = __ldg(&w[ti]);
        g_part[row] = make_float2(CONFIDENCE_F * nll * wt + SMOOTHING_F * smooth, wt);
    }
}

__global__ __launch_bounds__(1024)
void ls_final_kernel(float* __restrict__ out, int nrows)
{
    __shared__ float2 s[32];
    float ls = 0.f, ws = 0.f;
    for (int i = threadIdx.x; i < nrows; i += 1024) {
        float2 p = g_part[i];
        ls += p.x; ws += p.y;
    }
    #pragma unroll
    for (int o = 16; o; o >>= 1) {
        ls += __shfl_xor_sync(0xffffffff, ls, o);
        ws += __shfl_xor_sync(0xffffffff, ws, o);
    }
    int wid = threadIdx.x >> 5, lid = threadIdx.x & 31;
    if (lid == 0) s[wid] = make_float2(ls, ws);
    __syncthreads();
    if (threadIdx.x == 0) {
        float L = 0.f, W = 0.f;
        #pragma unroll
        for (int i = 0; i < 32; i++) { L += s[i].x; W += s[i].y; }
        out[0] = L / W;
    }
}

extern "C" void kernel_launch(void* const* d_in, const int* in_sizes, int n_in,
                              void* d_out, int out_size)
{
    // Identify inputs by element count, not position:
    //   x: B*2048 (largest), target: B (middle), weight: 2048 (smallest, == C_DIM)
    int ix = 0, it = 1, iw = 2;
    long long best = -1;
    for (int i = 0; i < n_in; i++)
        if ((long long)in_sizes[i] > best) { best = in_sizes[i]; ix = i; }
    long long small = best + 1;
    for (int i = 0; i < n_in; i++)
        if (i != ix && (long long)in_sizes[i] < small) { small = in_sizes[i]; iw = i; }
    for (int i = 0; i < n_in; i++)
        if (i != ix && i != iw) it = i;

    const float4* x   = (const float4*)d_in[ix];
    const void*   tgt = d_in[it];
    const float*  w   = (const float*)d_in[iw];
    float* out = (float*)d_out;

    int B = in_sizes[ix] / C_DIM;
    if (B > B_MAX) B = B_MAX;

    detect_t64_kernel<<<1, 1024>>>((const int*)tgt, B);
    ls_row_kernel<<<B, 256>>>(x, tgt, w);
    ls_final_kernel<<<1, 1024>>>(out, B);
}

// round 3
// speedup vs baseline: 1.7548x; 1.7548x over previous
#include <cuda_runtime.h>
#include <cuda_bf16.h>

#define CONFIDENCE_F 0.95f
#define SMOOTHING_F  0.05f
#define B_MAX 65536
#define C_DIM 2048                 // floats per row
#define F4_PER_ROW (C_DIM / 4)     // 512 float4

// Deterministic per-row partials (loss_i, w_i). __device__ global scratch.
__device__ float2 g_part[B_MAX];
__device__ int    g_is64;          // 1 if target buffer is int64, 0 if int32

// Detect target dtype by inspecting odd int32 words (safe under either dtype).
// int64 targets < 2048 -> every odd word is 0. 1024 odd words checked:
// P(all-zero | int32 targets) = 2048^-1024 ~ 0.
__global__ void detect_t64_kernel(const int* __restrict__ t, int nwords)
{
    __shared__ int any_nz;
    if (threadIdx.x == 0) any_nz = 0;
    __syncthreads();
    int lim = nwords < 2048 ? nwords : 2048;
    int local = 0;
    for (int i = 1 + 2 * threadIdx.x; i < lim; i += 2 * blockDim.x)
        if (t[i] != 0) local = 1;
    if (local) any_nz = 1;         // idempotent
    __syncthreads();
    if (threadIdx.x == 0) g_is64 = any_nz ? 0 : 1;
}

// Warp-per-row: 16 front-batched LDG.128 per thread (64 floats in registers),
// butterfly-shuffle reductions only. No smem, no __syncthreads.
__global__ __launch_bounds__(256)
void ls_row_kernel(const float4* __restrict__ x,
                   const void* __restrict__ tgt,
                   const float* __restrict__ w,
                   int B)
{
    const int warps_per_blk = blockDim.x >> 5;
    const int gwarp = blockIdx.x * warps_per_blk + (threadIdx.x >> 5);
    const int nwarp = gridDim.x * warps_per_blk;
    const int lane  = threadIdx.x & 31;
    const bool is64 = (g_is64 != 0);

    for (int row = gwarp; row < B; row += nwarp) {
        const float4* xr = x + (size_t)row * F4_PER_ROW;

        // Front-batched coalesced loads: MLP = 16
        float4 v[16];
        #pragma unroll
        for (int i = 0; i < 16; i++) v[i] = xr[lane + 32 * i];

        // Lane 0 fetches target index, x[row,ti] (L1 hit: this warp just
        // loaded the line), and weight. Overlaps with the vector-load wait.
        int ti = 0; float xt = 0.f, wt = 0.f;
        if (lane == 0) {
            ti = is64 ? (int)((const long long*)tgt)[row]
                      : ((const int*)tgt)[row];
            ti = min(max(ti, 0), C_DIM - 1);
            xt = ((const float*)x)[(size_t)row * C_DIM + ti];
            wt = __ldg(&w[ti]);
        }

        // max and sum(x), register tree
        float mx0 = -3.402823466e+38f, mx1 = mx0;
        float sx0 = 0.f, sx1 = 0.f;
        #pragma unroll
        for (int i = 0; i < 16; i += 2) {
            mx0 = fmaxf(mx0, fmaxf(fmaxf(v[i].x, v[i].y), fmaxf(v[i].z, v[i].w)));
            mx1 = fmaxf(mx1, fmaxf(fmaxf(v[i+1].x, v[i+1].y), fmaxf(v[i+1].z, v[i+1].w)));
            sx0 += (v[i].x + v[i].y) + (v[i].z + v[i].w);
            sx1 += (v[i+1].x + v[i+1].y) + (v[i+1].z + v[i+1].w);
        }
        float mx = fmaxf(mx0, mx1);
        float sx = sx0 + sx1;

        #pragma unroll
        for (int o = 16; o; o >>= 1)
            mx = fmaxf(mx, __shfl_xor_sync(0xffffffff, mx, o));

        // sum exp(x - mx) from registers, 2 accumulators for ILP
        float se0 = 0.f, se1 = 0.f;
        #pragma unroll
        for (int i = 0; i < 16; i += 2) {
            se0 += __expf(v[i].x - mx)   + __expf(v[i].y - mx)
                 + __expf(v[i].z - mx)   + __expf(v[i].w - mx);
            se1 += __expf(v[i+1].x - mx) + __expf(v[i+1].y - mx)
                 + __expf(v[i+1].z - mx) + __expf(v[i+1].w - mx);
        }
        float se = se0 + se1;

        #pragma unroll
        for (int o = 16; o; o >>= 1) {
            se += __shfl_xor_sync(0xffffffff, se, o);
            sx += __shfl_xor_sync(0xffffffff, sx, o);
        }

        if (lane == 0) {
            float lse    = mx + __logf(se);
            float nll    = lse - xt;                    // -logprob[target]
            float smooth = lse - sx * (1.0f / C_DIM);   // -mean(logprobs)
            g_part[row]  = make_float2(CONFIDENCE_F * nll * wt + SMOOTHING_F * smooth, wt);
        }
    }
}

__global__ __launch_bounds__(1024)
void ls_final_kernel(float* __restrict__ out, int nrows)
{
    __shared__ float2 s[32];
    const float4* p4 = (const float4*)g_part;   // two (loss,w) pairs per float4
    int npairs4 = nrows >> 1;
    float ls = 0.f, ws = 0.f;
    for (int i = threadIdx.x; i < npairs4; i += 1024) {
        float4 p = p4[i];
        ls += p.x + p.z;
        ws += p.y + p.w;
    }
    if ((nrows & 1) && threadIdx.x == 0) {
        float2 p = g_part[nrows - 1];
        ls += p.x; ws += p.y;
    }
    #pragma unroll
    for (int o = 16; o; o >>= 1) {
        ls += __shfl_xor_sync(0xffffffff, ls, o);
        ws += __shfl_xor_sync(0xffffffff, ws, o);
    }
    int wid = threadIdx.x >> 5, lid = threadIdx.x & 31;
    if (lid == 0) s[wid] = make_float2(ls, ws);
    __syncthreads();
    if (threadIdx.x == 0) {
        float L = 0.f, W = 0.f;
        #pragma unroll
        for (int i = 0; i < 32; i++) { L += s[i].x; W += s[i].y; }
        out[0] = L / W;
    }
}

extern "C" void kernel_launch(void* const* d_in, const int* in_sizes, int n_in,
                              void* d_out, int out_size)
{
    // Identify inputs by element count: x = largest, weight = smallest (2048),
    // target = the remaining one.
    int ix = 0, it = 1, iw = 2;
    long long best = -1;
    for (int i = 0; i < n_in; i++)
        if ((long long)in_sizes[i] > best) { best = in_sizes[i]; ix = i; }
    long long small = best + 1;
    for (int i = 0; i < n_in; i++)
        if (i != ix && (long long)in_sizes[i] < small) { small = in_sizes[i]; iw = i; }
    for (int i = 0; i < n_in; i++)
        if (i != ix && i != iw) it = i;

    const float4* x   = (const float4*)d_in[ix];
    const void*   tgt = d_in[it];
    const float*  w   = (const float*)d_in[iw];
    float* out = (float*)d_out;

    int B = in_sizes[ix] / C_DIM;
    if (B > B_MAX) B = B_MAX;

    // ~4 rows per warp via grid-stride
    int nblocks = (B / 4 + 7) / 8;          // warps = B/4, 8 warps/block
    if (nblocks < 148)  nblocks = 148;
    if (nblocks > 4096) nblocks = 4096;

    detect_t64_kernel<<<1, 256>>>((const int*)tgt, B);
    ls_row_kernel<<<nblocks, 256>>>(x, tgt, w, B);
    ls_final_kernel<<<1, 1024>>>(out, B);
}